// round 11
// baseline (speedup 1.0000x reference)
#include <cuda_runtime.h>
#include <math.h>

#define Bv 64
#define Tv 256
#define Ev 300
#define EP 304          // padded K for the input GEMMs (zeros in pad cols)
#define Hv 512
#define Ov 5
#define PADTOK 1
#define GROWS 2048      // 4*H gate rows
#define NCTA 128        // recurrent CTAs; each owns 4 hidden units = 16 gate rows

// ---------------- scratch (static device allocations; no cudaMalloc) ----------------
__device__ float g_inp [Tv*Bv*EP];                 // [t][b][e], e padded to 304, pad = 0
__device__ float g_ig  [Tv*NCTA*16*Bv];            // [t][c][rr][b]  (rr = u*4+q)
__device__ float g_Wblk[NCTA*Hv*16];               // [c][k][rr]
__device__ float g_hA  [Hv*Bv];                    // h ping  [j][b]
__device__ float g_hB  [Hv*Bv];                    // h pong  [j][b]
__device__ float g_c   [Hv*Bv];                    // c state [j][b]
__device__ float g_last[Bv*Hv];                    // [b][j]
__device__ float g_att [Tv*Bv];                    // [t][b]  (== index m = t*64+b)
__device__ float g_part2[Bv*Ev];                   // [b][e]  last-state part of attention layer 1
__device__ float g_H1  [Tv*Bv*Ev];                 // [m][e]  tanh(layer1)
__device__ int   g_len [Bv];

__device__ __forceinline__ float sigf(float x) { return 1.f / (1.f + expf(-x)); }

// ---------------- tiny kernels ----------------
__global__ void k_len(const int* __restrict__ x) {
    int b = threadIdx.x;
    if (b < Bv) {
        int c = 0;
        for (int t = 0; t < Tv; t++) c += (x[b*Tv + t] != PADTOK);
        g_len[b] = c;
    }
}

__global__ void k_embed(const float* __restrict__ emb, const int* __restrict__ x) {
    int idx = blockIdx.x * blockDim.x + threadIdx.x;
    if (idx >= Tv*Bv*EP) return;
    int e = idx % EP;
    int m = idx / EP;
    int b = m % Bv;
    int t = m / Bv;
    float v = 0.f;
    if (e < Ev) {
        int tok = x[b*Tv + t];
        if (tok != PADTOK) v = emb[(size_t)tok*Ev + e];   // padding_idx row -> 0
    }
    g_inp[idx] = v;
}

// permute W_hh[2048][512] -> g_Wblk[c][k][rr], rr = u*4+q, row = (4c+u) + q*512
__global__ void k_wblk(const float* __restrict__ Whh) {
    int idx = blockIdx.x * blockDim.x + threadIdx.x;
    if (idx >= NCTA*Hv*16) return;
    int rr = idx & 15;
    int k  = (idx >> 4) & (Hv - 1);
    int c  = idx >> 13;              // /(512*16)
    int u = rr >> 2, q = rr & 3;
    int r = (c*4 + u) + q*Hv;
    g_Wblk[idx] = Whh[(size_t)r*Hv + k];
}

__global__ void k_zero() {
    int i = blockIdx.x * blockDim.x + threadIdx.x;
    if (i < Hv*Bv) { g_hA[i] = 0.f; g_c[i] = 0.f; }
}

__global__ void k_reinit() {   // h <- last (transposed), c <- 0 for iteration 1
    int i = blockIdx.x * blockDim.x + threadIdx.x;
    if (i < Hv*Bv) {
        int j = i >> 6, b = i & 63;
        g_hA[i] = g_last[b*Hv + j];
        g_c[i] = 0.f;
    }
}

// ---------------- time-parallel GEMM: C[m][n] = sum_k g_inp[m][k] * B[n][k] ----------------
// mode 0: input gates -> g_ig scatter, bias = b_ih[n]+b_hh[n]    (N=2048, ldb=300)
// mode 1: attention layer1 -> g_H1 = tanh(acc + g_part2[b][n])   (N=300,  ldb=812)
__global__ void k_gemm(const float* __restrict__ B, const float* __restrict__ bias1,
                       const float* __restrict__ bias2, int N, int ldb, int mode) {
    __shared__ float As[16][68];
    __shared__ float Bs[16][68];
    int tid = threadIdx.x;
    int m0 = blockIdx.y * 64, n0 = blockIdx.x * 64;
    int tm = tid >> 2, ks = tid & 3;
    int tx = tid & 15, ty = tid >> 4;
    float acc[4][4] = {};

    for (int k0 = 0; k0 < EP; k0 += 16) {
        float4 a4 = *(const float4*)&g_inp[(size_t)(m0 + tm)*EP + k0 + ks*4];
        As[ks*4+0][tm] = a4.x; As[ks*4+1][tm] = a4.y;
        As[ks*4+2][tm] = a4.z; As[ks*4+3][tm] = a4.w;
        int n = n0 + tm;
        #pragma unroll
        for (int i = 0; i < 4; i++) {
            int k = k0 + ks*4 + i;
            float v = 0.f;
            if (n < N && k < Ev) v = B[(size_t)n*ldb + k];
            Bs[ks*4+i][tm] = v;
        }
        __syncthreads();
        #pragma unroll
        for (int kk = 0; kk < 16; kk++) {
            float4 a = *(const float4*)&As[kk][ty*4];
            float4 bb = *(const float4*)&Bs[kk][tx*4];
            acc[0][0] += a.x*bb.x; acc[0][1] += a.x*bb.y; acc[0][2] += a.x*bb.z; acc[0][3] += a.x*bb.w;
            acc[1][0] += a.y*bb.x; acc[1][1] += a.y*bb.y; acc[1][2] += a.y*bb.z; acc[1][3] += a.y*bb.w;
            acc[2][0] += a.z*bb.x; acc[2][1] += a.z*bb.y; acc[2][2] += a.z*bb.z; acc[2][3] += a.z*bb.w;
            acc[3][0] += a.w*bb.x; acc[3][1] += a.w*bb.y; acc[3][2] += a.w*bb.z; acc[3][3] += a.w*bb.w;
        }
        __syncthreads();
    }

    #pragma unroll
    for (int i = 0; i < 4; i++) {
        int m = m0 + ty*4 + i;
        int t = m >> 6, b = m & 63;
        #pragma unroll
        for (int j = 0; j < 4; j++) {
            int n = n0 + tx*4 + j;
            if (mode == 0) {
                float v = acc[i][j] + bias1[n] + bias2[n];
                int q = n >> 9, jj = n & (Hv - 1);
                int cc = jj >> 2, u = jj & 3, rr = u*4 + q;
                g_ig[(((size_t)t*NCTA + cc)*16 + rr)*64 + b] = v;
            } else if (n < Ev) {
                g_H1[(size_t)m*Ev + n] = tanhf(acc[i][j] + g_part2[b*Ev + n]);
            }
        }
    }
}

// part2[b][e] = ab1[e] + sum_k last[b][k] * aW1[e][300+k]
__global__ void k_part2(const float* __restrict__ aW1, const float* __restrict__ ab1) {
    int wid = (blockIdx.x * blockDim.x + threadIdx.x) >> 5;
    int lane = threadIdx.x & 31;
    if (wid >= Bv*Ev) return;
    int b = wid / Ev, e = wid % Ev;
    const float* lp = g_last + b*Hv;
    const float* wp = aW1 + (size_t)e*(Ev + Hv) + Ev;
    float s = 0.f;
    for (int k = lane; k < Hv; k += 32) s += lp[k] * wp[k];
    #pragma unroll
    for (int o = 16; o; o >>= 1) s += __shfl_xor_sync(0xffffffffu, s, o);
    if (!lane) g_part2[b*Ev + e] = s + ab1[e];
}

// att[m] = sigmoid(ab2 + sum_e H1[m][e]*aW2[e])
__global__ void k_att(const float* __restrict__ aW2, const float* __restrict__ ab2) {
    int wid = (blockIdx.x * blockDim.x + threadIdx.x) >> 5;
    int lane = threadIdx.x & 31;
    if (wid >= Tv*Bv) return;
    const float* hp = g_H1 + (size_t)wid*Ev;
    float s = 0.f;
    for (int e = lane; e < Ev; e += 32) s += hp[e] * aW2[e];
    #pragma unroll
    for (int o = 16; o; o >>= 1) s += __shfl_xor_sync(0xffffffffu, s, o);
    if (!lane) g_att[wid] = sigf(s + ab2[0]);
}

// ---------------- recurrent step: gates = ig + Whh@h ; LSTM cell (+ optional att gate) ----------------
__global__ void k_step(int t, int use_att, int parity) {
    __shared__ float Hs[64*64];   // [kk][b]
    __shared__ float Ws[64*16];   // [kk][rr]
    __shared__ float Gs[16*64];   // gates [rr][b]
    const float* __restrict__ hin = parity ? g_hB : g_hA;
    float* __restrict__ hout      = parity ? g_hA : g_hB;

    int tid = threadIdx.x, w = tid >> 5, lane = tid & 31;
    int c = blockIdx.x;

    const float* igc = g_ig + ((size_t)t*NCTA + c)*1024;
    float acc[4][2];
    #pragma unroll
    for (int i = 0; i < 4; i++) {
        float2 v = *(const float2*)&igc[(w*4 + i)*64 + 2*lane];
        acc[i][0] = v.x; acc[i][1] = v.y;
    }

    for (int k0 = 0; k0 < Hv; k0 += 64) {
        __syncthreads();
        const float4* hs = (const float4*)(hin + k0*64);
        float4* hd = (float4*)Hs;
        #pragma unroll
        for (int i = tid; i < 1024; i += 128) hd[i] = hs[i];
        const float4* ws = (const float4*)(g_Wblk + ((size_t)c*Hv + k0)*16);
        float4* wd = (float4*)Ws;
        #pragma unroll
        for (int i = tid; i < 256; i += 128) wd[i] = ws[i];
        __syncthreads();
        #pragma unroll 16
        for (int kk = 0; kk < 64; kk++) {
            float2 h2 = *(const float2*)&Hs[kk*64 + 2*lane];
            float4 w4 = *(const float4*)&Ws[kk*16 + w*4];
            acc[0][0] += w4.x*h2.x; acc[0][1] += w4.x*h2.y;
            acc[1][0] += w4.y*h2.x; acc[1][1] += w4.y*h2.y;
            acc[2][0] += w4.z*h2.x; acc[2][1] += w4.z*h2.y;
            acc[3][0] += w4.w*h2.x; acc[3][1] += w4.w*h2.y;
        }
    }

    #pragma unroll
    for (int i = 0; i < 4; i++) {
        Gs[(w*4 + i)*64 + 2*lane]     = acc[i][0];
        Gs[(w*4 + i)*64 + 2*lane + 1] = acc[i][1];
    }
    __syncthreads();

    for (int idx = tid; idx < 256; idx += 128) {
        int u = idx >> 6, b = idx & 63;
        float gi = Gs[(u*4 + 0)*64 + b];
        float gf = Gs[(u*4 + 1)*64 + b];
        float gg = Gs[(u*4 + 2)*64 + b];
        float go = Gs[(u*4 + 3)*64 + b];
        int j = c*4 + u;
        float cold = g_c[j*64 + b];
        float cn = sigf(gf)*cold + sigf(gi)*tanhf(gg);
        float hn = sigf(go)*tanhf(cn);
        if (use_att) {
            float a = g_att[t*64 + b];
            hn = a*hn + (1.f - a)*hin[j*64 + b];
            cn = a*cn + (1.f - a)*cold;
        }
        g_c[j*64 + b] = cn;
        hout[j*64 + b] = hn;
        if (t == g_len[b] - 1) g_last[b*Hv + j] = hn;
    }
}

__global__ void k_logits(const float* __restrict__ Wout, const float* __restrict__ bout,
                         float* __restrict__ out) {
    int wid = (blockIdx.x * blockDim.x + threadIdx.x) >> 5;
    int lane = threadIdx.x & 31;
    if (wid >= Bv*Ov) return;
    int b = wid / Ov, o = wid % Ov;
    float s = 0.f;
    for (int j = lane; j < Hv; j += 32) s += g_last[b*Hv + j] * Wout[(size_t)o*Hv + j];
    #pragma unroll
    for (int off = 16; off; off >>= 1) s += __shfl_xor_sync(0xffffffffu, s, off);
    if (!lane) out[b*Ov + o] = s + bout[o];
}

// ---------------- launch ----------------
extern "C" void kernel_launch(void* const* d_in, const int* in_sizes, int n_in,
                              void* d_out, int out_size) {
    const float* emb  = (const float*)d_in[0];
    const float* Wih  = (const float*)d_in[1];
    const float* bih  = (const float*)d_in[2];
    const float* Whh  = (const float*)d_in[3];
    const float* bhh  = (const float*)d_in[4];
    const float* aW1  = (const float*)d_in[5];
    const float* ab1  = (const float*)d_in[6];
    const float* aW2  = (const float*)d_in[7];
    const float* ab2  = (const float*)d_in[8];
    const float* Wout = (const float*)d_in[9];
    const float* bout = (const float*)d_in[10];
    const int*   x    = (const int*)d_in[11];
    float* out = (float*)d_out;
    (void)in_sizes; (void)n_in; (void)out_size;

    k_len<<<1, 64>>>(x);
    k_embed<<<(Tv*Bv*EP + 255)/256, 256>>>(emb, x);
    k_wblk<<<(NCTA*Hv*16 + 255)/256, 256>>>(Whh);

    // one GEMM feeds both iterations (input-side gates are time-invariant across iters)
    dim3 gig(GROWS/64, Tv*Bv/64);
    k_gemm<<<gig, 256>>>(Wih, bih, bhh, GROWS, Ev, 0);

    // ---- iteration 0 ----
    k_zero<<<(Hv*Bv + 255)/256, 256>>>();
    for (int t = 0; t < Tv; t++)
        k_step<<<NCTA, 128>>>(t, 0, t & 1);

    // ---- attention (uses g_last from iter 0) ----
    k_part2<<<(Bv*Ev*32 + 255)/256, 256>>>(aW1, ab1);
    dim3 gh1((Ev + 63)/64, Tv*Bv/64);
    k_gemm<<<gh1, 256>>>(aW1, (const float*)0, (const float*)0, Ev, Ev + Hv, 1);
    k_att<<<(Tv*Bv*32 + 255)/256, 256>>>(aW2, ab2);

    // ---- iteration 1 ----
    k_reinit<<<(Hv*Bv + 255)/256, 256>>>();
    for (int t = 0; t < Tv; t++)
        k_step<<<NCTA, 128>>>(t, 1, t & 1);

    k_logits<<<(Bv*Ov*32 + 255)/256, 256>>>(Wout, bout, out);
}

// round 12
// speedup vs baseline: 2.7806x; 2.7806x over previous
#include <cuda_runtime.h>
#include <math.h>
#include <stdint.h>

#define Bv 64
#define Tv 256
#define Ev 300
#define EP 304          // padded K for the input GEMMs (zeros in pad cols)
#define Hv 512
#define Ov 5
#define PADTOK 1
#define GROWS 2048      // 4*H gate rows
#define NCTA 128        // recurrent CTAs; each owns 4 hidden units = 16 gate rows

// ---------------- scratch (static device allocations; no cudaMalloc) ----------------
__device__ float g_inp [Tv*Bv*EP];                 // [t][b][e], e padded to 304, pad = 0
__device__ float g_ig  [Tv*NCTA*16*Bv];            // [t][c][rr][b]  (rr = u*4+q)
__device__ float g_Wblk[NCTA*Hv*16];               // [c][k][rr]
__device__ float g_hA  [Hv*Bv];                    // h ping  [j][b]
__device__ float g_hB  [Hv*Bv];                    // h pong  [j][b]
__device__ float g_last[Bv*Hv];                    // [b][j]
__device__ float g_att [Tv*Bv];                    // [t][b]
__device__ float g_part2[Bv*Ev];                   // [b][e]
__device__ float g_H1  [Tv*Bv*Ev];                 // [m][e]  tanh(layer1)
__device__ int   g_len [Bv];
__device__ int   g_bar;                            // grid barrier counter

__device__ __forceinline__ float sigf(float x) { return 1.f / (1.f + expf(-x)); }

__device__ __forceinline__ uint32_t smem_u32(const void* p) {
    uint32_t a;
    asm("{ .reg .u64 t; cvta.to.shared.u64 t, %1; cvt.u32.u64 %0, t; }" : "=r"(a) : "l"(p));
    return a;
}

// ---------------- tiny kernels ----------------
__global__ void k_len(const int* __restrict__ x) {
    int b = threadIdx.x;
    if (b < Bv) {
        int c = 0;
        for (int t = 0; t < Tv; t++) c += (x[b*Tv + t] != PADTOK);
        g_len[b] = c;
    }
}

__global__ void k_embed(const float* __restrict__ emb, const int* __restrict__ x) {
    int idx = blockIdx.x * blockDim.x + threadIdx.x;
    if (idx >= Tv*Bv*EP) return;
    int e = idx % EP;
    int m = idx / EP;
    int b = m % Bv;
    int t = m / Bv;
    float v = 0.f;
    if (e < Ev) {
        int tok = x[b*Tv + t];
        if (tok != PADTOK) v = emb[(size_t)tok*Ev + e];   // padding_idx row -> 0
    }
    g_inp[idx] = v;
}

// permute W_hh[2048][512] -> g_Wblk[c][k][rr], rr = u*4+q, row = (4c+u) + q*512
__global__ void k_wblk(const float* __restrict__ Whh) {
    int idx = blockIdx.x * blockDim.x + threadIdx.x;
    if (idx >= NCTA*Hv*16) return;
    int rr = idx & 15;
    int k  = (idx >> 4) & (Hv - 1);
    int c  = idx >> 13;
    int u = rr >> 2, q = rr & 3;
    int r = (c*4 + u) + q*Hv;
    g_Wblk[idx] = Whh[(size_t)r*Hv + k];
}

__global__ void k_zero() {
    int i = blockIdx.x * blockDim.x + threadIdx.x;
    if (i == 0) g_bar = 0;
    if (i < Hv*Bv) g_hA[i] = 0.f;
}

__global__ void k_reinit() {   // h <- last (transposed) for iteration 1
    int i = blockIdx.x * blockDim.x + threadIdx.x;
    if (i == 0) g_bar = 0;
    if (i < Hv*Bv) {
        int j = i >> 6, b = i & 63;
        g_hA[i] = g_last[b*Hv + j];
    }
}

// ---------------- time-parallel GEMM: C[m][n] = sum_k g_inp[m][k] * B[n][k] ----------------
__global__ void k_gemm(const float* __restrict__ B, const float* __restrict__ bias1,
                       const float* __restrict__ bias2, int N, int ldb, int mode) {
    __shared__ float As[16][68];
    __shared__ float Bs[16][68];
    int tid = threadIdx.x;
    int m0 = blockIdx.y * 64, n0 = blockIdx.x * 64;
    int tm = tid >> 2, ks = tid & 3;
    int tx = tid & 15, ty = tid >> 4;
    float acc[4][4] = {};

    for (int k0 = 0; k0 < EP; k0 += 16) {
        float4 a4 = *(const float4*)&g_inp[(size_t)(m0 + tm)*EP + k0 + ks*4];
        As[ks*4+0][tm] = a4.x; As[ks*4+1][tm] = a4.y;
        As[ks*4+2][tm] = a4.z; As[ks*4+3][tm] = a4.w;
        int n = n0 + tm;
        #pragma unroll
        for (int i = 0; i < 4; i++) {
            int k = k0 + ks*4 + i;
            float v = 0.f;
            if (n < N && k < Ev) v = B[(size_t)n*ldb + k];
            Bs[ks*4+i][tm] = v;
        }
        __syncthreads();
        #pragma unroll
        for (int kk = 0; kk < 16; kk++) {
            float4 a = *(const float4*)&As[kk][ty*4];
            float4 bb = *(const float4*)&Bs[kk][tx*4];
            acc[0][0] += a.x*bb.x; acc[0][1] += a.x*bb.y; acc[0][2] += a.x*bb.z; acc[0][3] += a.x*bb.w;
            acc[1][0] += a.y*bb.x; acc[1][1] += a.y*bb.y; acc[1][2] += a.y*bb.z; acc[1][3] += a.y*bb.w;
            acc[2][0] += a.z*bb.x; acc[2][1] += a.z*bb.y; acc[2][2] += a.z*bb.z; acc[2][3] += a.z*bb.w;
            acc[3][0] += a.w*bb.x; acc[3][1] += a.w*bb.y; acc[3][2] += a.w*bb.z; acc[3][3] += a.w*bb.w;
        }
        __syncthreads();
    }

    #pragma unroll
    for (int i = 0; i < 4; i++) {
        int m = m0 + ty*4 + i;
        int t = m >> 6, b = m & 63;
        #pragma unroll
        for (int j = 0; j < 4; j++) {
            int n = n0 + tx*4 + j;
            if (mode == 0) {
                float v = acc[i][j] + bias1[n] + bias2[n];
                int q = n >> 9, jj = n & (Hv - 1);
                int cc = jj >> 2, u = jj & 3, rr = u*4 + q;
                g_ig[(((size_t)t*NCTA + cc)*16 + rr)*64 + b] = v;
            } else if (n < Ev) {
                g_H1[(size_t)m*Ev + n] = tanhf(acc[i][j] + g_part2[b*Ev + n]);
            }
        }
    }
}

// part2[b][e] = ab1[e] + sum_k last[b][k] * aW1[e][300+k]
__global__ void k_part2(const float* __restrict__ aW1, const float* __restrict__ ab1) {
    int wid = (blockIdx.x * blockDim.x + threadIdx.x) >> 5;
    int lane = threadIdx.x & 31;
    if (wid >= Bv*Ev) return;
    int b = wid / Ev, e = wid % Ev;
    const float* lp = g_last + b*Hv;
    const float* wp = aW1 + (size_t)e*(Ev + Hv) + Ev;
    float s = 0.f;
    for (int k = lane; k < Hv; k += 32) s += lp[k] * wp[k];
    #pragma unroll
    for (int o = 16; o; o >>= 1) s += __shfl_xor_sync(0xffffffffu, s, o);
    if (!lane) g_part2[b*Ev + e] = s + ab1[e];
}

// att[m] = sigmoid(ab2 + sum_e H1[m][e]*aW2[e])
__global__ void k_att(const float* __restrict__ aW2, const float* __restrict__ ab2) {
    int wid = (blockIdx.x * blockDim.x + threadIdx.x) >> 5;
    int lane = threadIdx.x & 31;
    if (wid >= Tv*Bv) return;
    const float* hp = g_H1 + (size_t)wid*Ev;
    float s = 0.f;
    for (int e = lane; e < Ev; e += 32) s += hp[e] * aW2[e];
    #pragma unroll
    for (int o = 16; o; o >>= 1) s += __shfl_xor_sync(0xffffffffu, s, o);
    if (!lane) g_att[wid] = sigf(s + ab2[0]);
}

// ---------------- persistent recurrent kernel: all 256 steps in one launch ----------------
// 128 CTAs x 128 threads. CTA c owns hidden units 4c..4c+3 (16 gate rows).
// W slice (32KB), c-state, own-h slice live in SMEM for the whole launch.
// h exchanged via global ping-pong with cp.async.cg (L2-coherent) + software grid barrier.
__device__ __forceinline__ void cp_chunk16k(uint32_t sdst, const float* gsrc, int tid) {
    const char* g = (const char*)gsrc + tid*16;
    uint32_t s = sdst + tid*16;
    #pragma unroll
    for (int i = 0; i < 8; i++)
        asm volatile("cp.async.cg.shared.global [%0], [%1], 16;\n"
                     :: "r"(s + i*2048), "l"(g + i*2048));
    asm volatile("cp.async.commit_group;\n" ::: "memory");
}

__global__ void __launch_bounds__(128, 1) k_persist(int use_att) {
    extern __shared__ float sm[];
    float* Wsm = sm;                 // 8192 : [k][rr] for this CTA
    float* Hb  = sm + 8192;          // 2 x 4096 : h chunk double buffer [kk][b]
    float* Gs  = sm + 16384;         // 1024 : gates [rr][b]
    float* csm = sm + 17408;         // 256  : c state [u][b]
    float* hpr = sm + 17664;         // 256  : own previous h [u][b]
    int*   len = (int*)(sm + 17920); // 64

    int tid = threadIdx.x, w = tid >> 5, lane = tid & 31;
    int c = blockIdx.x;
    uint32_t hb_u32 = smem_u32(Hb);

    { // resident W load (once per launch, reused 256 steps)
        const float4* ws = (const float4*)(g_Wblk + (size_t)c*8192);
        float4* wd = (float4*)Wsm;
        #pragma unroll
        for (int i = tid; i < 2048; i += 128) wd[i] = ws[i];
    }
    for (int idx = tid; idx < 256; idx += 128) {
        csm[idx] = 0.f;
        int u = idx >> 6, b = idx & 63;
        hpr[idx] = g_hA[(c*4 + u)*64 + b];
    }
    if (tid < 64) len[tid] = g_len[tid];
    __syncthreads();

    for (int t = 0; t < Tv; t++) {
        const float* hin = (t & 1) ? g_hB : g_hA;
        float*       hout = (t & 1) ? g_hA : g_hB;

        // input-side gates for this step (immutable, L1-cacheable)
        const float* igc = g_ig + ((size_t)t*NCTA + c)*1024;
        float2 ig[4];
        #pragma unroll
        for (int i = 0; i < 4; i++)
            ig[i] = *(const float2*)&igc[(w*4 + i)*64 + 2*lane];

        float acc[4][2] = {};

        // prefetch h chunk 0
        cp_chunk16k(hb_u32, hin, tid);

        #pragma unroll 1
        for (int ch = 0; ch < 8; ch++) {
            __syncthreads();   // target buffer free
            if (ch < 7) {
                cp_chunk16k(hb_u32 + (((ch + 1) & 1) * 4096) * 4, hin + (ch + 1)*4096, tid);
                asm volatile("cp.async.wait_group 1;\n" ::: "memory");
            } else {
                asm volatile("cp.async.wait_group 0;\n" ::: "memory");
            }
            __syncthreads();   // chunk visible to all threads
            const float* Hs = Hb + (ch & 1)*4096;
            const float* Wp = Wsm + ch*1024 + w*4;
            #pragma unroll 16
            for (int kk = 0; kk < 64; kk++) {
                float2 h2 = *(const float2*)&Hs[kk*64 + 2*lane];
                float4 w4 = *(const float4*)&Wp[kk*16];
                acc[0][0] += w4.x*h2.x; acc[0][1] += w4.x*h2.y;
                acc[1][0] += w4.y*h2.x; acc[1][1] += w4.y*h2.y;
                acc[2][0] += w4.z*h2.x; acc[2][1] += w4.z*h2.y;
                acc[3][0] += w4.w*h2.x; acc[3][1] += w4.w*h2.y;
            }
        }

        // stage gates
        #pragma unroll
        for (int i = 0; i < 4; i++) {
            Gs[(w*4 + i)*64 + 2*lane]     = acc[i][0] + ig[i].x;
            Gs[(w*4 + i)*64 + 2*lane + 1] = acc[i][1] + ig[i].y;
        }
        __syncthreads();

        // LSTM cell (+ optional attention gate)
        for (int idx = tid; idx < 256; idx += 128) {
            int u = idx >> 6, b = idx & 63;
            float gi = Gs[(u*4 + 0)*64 + b];
            float gf = Gs[(u*4 + 1)*64 + b];
            float gg = Gs[(u*4 + 2)*64 + b];
            float go = Gs[(u*4 + 3)*64 + b];
            float cold = csm[idx];
            float cn = sigf(gf)*cold + sigf(gi)*tanhf(gg);
            float hn = sigf(go)*tanhf(cn);
            if (use_att) {
                float a = g_att[t*64 + b];
                hn = a*hn + (1.f - a)*hpr[idx];
                cn = a*cn + (1.f - a)*cold;
            }
            csm[idx] = cn;
            hpr[idx] = hn;
            int j = c*4 + u;
            __stcg(&hout[j*64 + b], hn);
            if (t == len[b] - 1) g_last[b*Hv + j] = hn;
        }
        __syncthreads();   // all stores of this step issued before leader releases

        if (t < Tv - 1) {  // grid barrier
            if (tid == 0) {
                __threadfence();
                atomicAdd(&g_bar, 1);
                int tgt = NCTA * (t + 1);
                while (*(volatile int*)&g_bar < tgt) { }
                __threadfence();
            }
            __syncthreads();
        }
    }
}

__global__ void k_logits(const float* __restrict__ Wout, const float* __restrict__ bout,
                         float* __restrict__ out) {
    int wid = (blockIdx.x * blockDim.x + threadIdx.x) >> 5;
    int lane = threadIdx.x & 31;
    if (wid >= Bv*Ov) return;
    int b = wid / Ov, o = wid % Ov;
    float s = 0.f;
    for (int j = lane; j < Hv; j += 32) s += g_last[b*Hv + j] * Wout[(size_t)o*Hv + j];
    #pragma unroll
    for (int off = 16; off; off >>= 1) s += __shfl_xor_sync(0xffffffffu, s, off);
    if (!lane) out[b*Ov + o] = s + bout[o];
}

// ---------------- launch ----------------
extern "C" void kernel_launch(void* const* d_in, const int* in_sizes, int n_in,
                              void* d_out, int out_size) {
    const float* emb  = (const float*)d_in[0];
    const float* Wih  = (const float*)d_in[1];
    const float* bih  = (const float*)d_in[2];
    const float* Whh  = (const float*)d_in[3];
    const float* bhh  = (const float*)d_in[4];
    const float* aW1  = (const float*)d_in[5];
    const float* ab1  = (const float*)d_in[6];
    const float* aW2  = (const float*)d_in[7];
    const float* ab2  = (const float*)d_in[8];
    const float* Wout = (const float*)d_in[9];
    const float* bout = (const float*)d_in[10];
    const int*   x    = (const int*)d_in[11];
    float* out = (float*)d_out;
    (void)in_sizes; (void)n_in; (void)out_size;

    static int smem_set = 0;
    const int PSMEM = 17984 * 4;
    if (!smem_set) {
        cudaFuncSetAttribute(k_persist, cudaFuncAttributeMaxDynamicSharedMemorySize, PSMEM);
        smem_set = 1;
    }

    k_len<<<1, 64>>>(x);
    k_embed<<<(Tv*Bv*EP + 255)/256, 256>>>(emb, x);
    k_wblk<<<(NCTA*Hv*16 + 255)/256, 256>>>(Whh);

    // one GEMM feeds both iterations (input-side gates are time-invariant across iters)
    dim3 gig(GROWS/64, Tv*Bv/64);
    k_gemm<<<gig, 256>>>(Wih, bih, bhh, GROWS, Ev, 0);

    // ---- iteration 0 (persistent) ----
    k_zero<<<(Hv*Bv + 255)/256, 256>>>();
    k_persist<<<NCTA, 128, PSMEM>>>(0);

    // ---- attention (uses g_last from iter 0) ----
    k_part2<<<(Bv*Ev*32 + 255)/256, 256>>>(aW1, ab1);
    dim3 gh1((Ev + 63)/64, Tv*Bv/64);
    k_gemm<<<gh1, 256>>>(aW1, (const float*)0, (const float*)0, Ev, Ev + Hv, 1);
    k_att<<<(Tv*Bv*32 + 255)/256, 256>>>(aW2, ab2);

    // ---- iteration 1 (persistent) ----
    k_reinit<<<(Hv*Bv + 255)/256, 256>>>();
    k_persist<<<NCTA, 128, PSMEM>>>(1);

    k_logits<<<(Bv*Ov*32 + 255)/256, 256>>>(Wout, bout, out);
}